// round 16
// baseline (speedup 1.0000x reference)
#include <cuda_runtime.h>
#include <cuda_fp16.h>
#include <cstdint>

#define NS 1024
#define ND 256
#define NH 8
#define HD 2048

// ---------------- scratch (static device memory; no allocs) ----------------
__device__ __half g_Xh[2097152];
__device__ __half g_Wqh[524288], g_Wkh[524288], g_Wvh[524288], g_Wph[524288];
__device__ __half g_Qh[16777216], g_Kh[16777216];
__device__ __half g_Vth[16777216];                                // V transposed [bh, e, t]
__device__ __half g_Ph[67108864];                                 // fp16 logits -> probs (in place)
__device__ __half g_Oh[16777216];                                 // [B*S, H*D] concat layout

// ---------------- helpers ----------------
__device__ __forceinline__ uint32_t smem_u32(const void* p) {
    uint32_t a;
    asm("{ .reg .u64 t; cvta.to.shared.u64 t, %1; cvt.u32.u64 %0, t; }" : "=r"(a) : "l"(p));
    return a;
}

__device__ __forceinline__ uint32_t pack2h(float a, float b) {
    __half h0 = __float2half_rn(a), h1 = __float2half_rn(b);
    return (uint32_t)__half_as_ushort(h0) | ((uint32_t)__half_as_ushort(h1) << 16);
}

#define CP_ASYNC16(saddr, gptr) \
    asm volatile("cp.async.cg.shared.global [%0], [%1], 16;" :: "r"(saddr), "l"(gptr))
#define CP_COMMIT() asm volatile("cp.async.commit_group;")
#define CP_WAIT1()  asm volatile("cp.async.wait_group 1;")
#define CP_WAIT0()  asm volatile("cp.async.wait_group 0;")
#define LDMX4(r0, r1, r2, r3, addr) \
    asm volatile("ldmatrix.sync.aligned.m8n8.x4.shared.b16 {%0,%1,%2,%3}, [%4];" \
        : "=r"(r0), "=r"(r1), "=r"(r2), "=r"(r3) : "r"(addr))
#define MMA16816(acc, af, b0, b1) \
    asm volatile("mma.sync.aligned.m16n8k16.row.col.f32.f16.f16.f32 " \
        "{%0,%1,%2,%3}, {%4,%5,%6,%7}, {%8,%9}, {%0,%1,%2,%3};" \
        : "+f"((acc)[0]), "+f"((acc)[1]), "+f"((acc)[2]), "+f"((acc)[3]) \
        : "r"((af)[0]), "r"((af)[1]), "r"((af)[2]), "r"((af)[3]), "r"(b0), "r"(b1))

// ---------------------------------------------------------------------------
// Single-product fp16 GEMM mainloop (NF=4): C[128,128] NT, fp32 accum.
// 8 warps 2(M) x 4(N); warp tile 64 x 32.  BK=32.  3-stage cp.async ring,
// register pointer rotation, precomputed offsets, one barrier per chunk.
// Stage layout (bytes): sA [128][40]h @0 (10240), sB [128][40]h @10240.
// STAGE = 20480.  Sized for 2 CTAs/SM (acc = 64 regs).
// ---------------------------------------------------------------------------
__device__ __forceinline__ void mma_gemm1(
    const __half* __restrict__ A, const __half* __restrict__ B,
    int ldA, int ldB, int ksteps, float acc[4][4][4], char* sm)
{
    constexpr int STAGE = 20480;

    int t = threadIdx.x;
    int lane = t & 31, wid = t >> 5;
    int wm = wid & 1, wn = wid >> 1;

    #pragma unroll
    for (int mf = 0; mf < 4; mf++)
        #pragma unroll
        for (int nf = 0; nf < 4; nf++)
            #pragma unroll
            for (int e = 0; e < 4; e++) acc[mf][nf][e] = 0.f;

    uint32_t sb = smem_u32(sm);

    int r1 = t >> 2,          q1 = t & 3;
    int r2 = (t + 256) >> 2,  q2 = (t + 256) & 3;
    uint32_t stA1 = (uint32_t)(r1 * 80 + q1 * 16);
    uint32_t stA2 = (uint32_t)(r2 * 80 + q2 * 16);
    uint32_t stB1 = 10240 + stA1;
    uint32_t stB2 = 10240 + stA2;

    const __half* gA1 = A + (size_t)r1 * ldA + q1 * 8;
    const __half* gA2 = A + (size_t)r2 * ldA + q2 * 8;
    const __half* gB1 = B + (size_t)r1 * ldB + q1 * 8;
    const __half* gB2 = B + (size_t)r2 * ldB + q2 * 8;

    uint32_t aoff[2][4], boff[2][2];
    #pragma unroll
    for (int k16 = 0; k16 < 2; k16++) {
        #pragma unroll
        for (int mf = 0; mf < 4; mf++) {
            int row = wm * 64 + mf * 16 + (lane & 15);
            int ko  = k16 * 16 + (lane >> 4) * 8;
            aoff[k16][mf] = (uint32_t)(row * 80 + ko * 2);
        }
        #pragma unroll
        for (int p = 0; p < 2; p++) {
            int nrow = wn * 32 + p * 16 + (lane & 7) + ((lane >> 4) << 3);
            int ko   = k16 * 16 + ((lane >> 3) & 1) * 8;
            boff[k16][p] = (uint32_t)(10240 + nrow * 80 + ko * 2);
        }
    }

    auto load_tile = [&](uint32_t base) {
        CP_ASYNC16(base + stA1, gA1);
        CP_ASYNC16(base + stA2, gA2);
        CP_ASYNC16(base + stB1, gB1);
        CP_ASYNC16(base + stB2, gB2);
        CP_COMMIT();
        gA1 += 32; gA2 += 32; gB1 += 32; gB2 += 32;
    };

    uint32_t s0 = sb, s1 = sb + STAGE, s2 = sb + 2 * STAGE;
    load_tile(s0);
    if (ksteps > 1) load_tile(s1);

    for (int c = 0; c < ksteps; c++) {
        if (c + 1 < ksteps) { CP_WAIT1(); }
        else                { CP_WAIT0(); }
        __syncthreads();
        if (c + 2 < ksteps) load_tile(s2);

        #pragma unroll
        for (int k16 = 0; k16 < 2; k16++) {
            uint32_t af[4][4];
            #pragma unroll
            for (int mf = 0; mf < 4; mf++)
                LDMX4(af[mf][0], af[mf][1], af[mf][2], af[mf][3], s0 + aoff[k16][mf]);
            uint32_t bf[4][2];
            #pragma unroll
            for (int p = 0; p < 2; p++) {
                uint32_t rr0, rr1, rr2, rr3;
                LDMX4(rr0, rr1, rr2, rr3, s0 + boff[k16][p]);
                bf[2*p][0] = rr0; bf[2*p][1] = rr1;
                bf[2*p+1][0] = rr2; bf[2*p+1][1] = rr3;
            }
            #pragma unroll
            for (int mf = 0; mf < 4; mf++)
                #pragma unroll
                for (int nf = 0; nf < 4; nf++)
                    MMA16816(acc[mf][nf], af[mf], bf[nf][0], bf[nf][1]);
        }
        uint32_t tmp = s0; s0 = s1; s1 = s2; s2 = tmp;
    }
}

#define SMEM_G (3 * 20480)            // 61440
#define SMEM_S (SMEM_G + 5120)        // + rmax/rsum/Mrow/Srow

// ---------------------------------------------------------------------------
// Kernel: fused fp32 -> fp16 convert for all 5 inputs.  grid 4096, block 256
// ---------------------------------------------------------------------------
__global__ __launch_bounds__(256) void cvt_all(
    const float* __restrict__ x,  const float* __restrict__ Wq,
    const float* __restrict__ Wk, const float* __restrict__ Wv,
    const float* __restrict__ Wp)
{
    int blk = blockIdx.x;
    const float* src;
    __half* dst;
    int local;
    if (blk < 2048)      { src = x;  dst = g_Xh;  local = blk; }
    else if (blk < 2560) { src = Wq; dst = g_Wqh; local = blk - 2048; }
    else if (blk < 3072) { src = Wk; dst = g_Wkh; local = blk - 2560; }
    else if (blk < 3584) { src = Wv; dst = g_Wvh; local = blk - 3072; }
    else                 { src = Wp; dst = g_Wph; local = blk - 3584; }
    int i = local * 256 + threadIdx.x;
    float4 v = *(const float4*)(src + 4 * (size_t)i);
    *(uint2*)((char*)dst + 8 * (size_t)i) = make_uint2(pack2h(v.x, v.y), pack2h(v.z, v.w));
}

// ---------------------------------------------------------------------------
// Kernel: QKV projection.  grid (8, 2, 192): z = qkv*64 + b*8 + h
// Q pre-scaled by 2^-4 (exact).  V stored TRANSPOSED into g_Vth via smem.
// ---------------------------------------------------------------------------
__global__ __launch_bounds__(256, 2) void qkv_g(
    const float* __restrict__ bq, const float* __restrict__ bk, const float* __restrict__ bv)
{
    extern __shared__ char sm[];
    int z = blockIdx.z, qkv = z >> 6, bh = z & 63, b = bh >> 3, h = bh & 7;
    int m0 = blockIdx.x * 128, n0 = blockIdx.y * 128;

    const __half* Wh = (qkv == 0) ? g_Wqh : (qkv == 1) ? g_Wkh : g_Wvh;
    const float* bias = ((qkv == 0) ? bq : (qkv == 1) ? bk : bv) + h * ND + n0;

    float acc[4][4][4];
    mma_gemm1(g_Xh + ((size_t)b * NS + m0) * ND,
              Wh + (size_t)h * ND * ND + (size_t)n0 * ND, ND, ND, 8, acc, sm);

    int lane = threadIdx.x & 31, wid = threadIdx.x >> 5;
    int wm = wid & 1, wn = wid >> 1;

    if (qkv < 2) {
        __half* Oh = (qkv == 0) ? g_Qh : g_Kh;
        float scale = (qkv == 0) ? 0.0625f : 1.0f;
        #pragma unroll
        for (int mf = 0; mf < 4; mf++) {
            int r = m0 + wm * 64 + mf * 16 + (lane >> 2);
            #pragma unroll
            for (int nf = 0; nf < 4; nf++) {
                int cc = wn * 32 + nf * 8 + ((lane & 3) << 1);
                float2 bb = *(const float2*)(bias + cc);
                size_t base0 = ((size_t)bh * NS + r) * ND + n0 + cc;
                size_t base1 = base0 + 8 * ND;
                *(uint32_t*)(Oh + base0) = pack2h((acc[mf][nf][0] + bb.x) * scale,
                                                  (acc[mf][nf][1] + bb.y) * scale);
                *(uint32_t*)(Oh + base1) = pack2h((acc[mf][nf][2] + bb.x) * scale,
                                                  (acc[mf][nf][3] + bb.y) * scale);
            }
        }
    } else {
        __syncthreads();
        __half* tsm = (__half*)sm;            // [128][130] halves
        #pragma unroll
        for (int mf = 0; mf < 4; mf++) {
            int rl = wm * 64 + mf * 16 + (lane >> 2);
            #pragma unroll
            for (int nf = 0; nf < 4; nf++) {
                int cc = wn * 32 + nf * 8 + ((lane & 3) << 1);
                float2 bb = *(const float2*)(bias + cc);
                *(uint32_t*)(tsm + (size_t)rl * 130 + cc) =
                    pack2h(acc[mf][nf][0] + bb.x, acc[mf][nf][1] + bb.y);
                *(uint32_t*)(tsm + (size_t)(rl + 8) * 130 + cc) =
                    pack2h(acc[mf][nf][2] + bb.x, acc[mf][nf][3] + bb.y);
            }
        }
        __syncthreads();
        #pragma unroll
        for (int j = 0; j < 16; j++) {
            int er = wid * 16 + j;
            int s = lane * 4;
            uint32_t p0 = pack2h(__half2float(tsm[(size_t)(s + 0) * 130 + er]),
                                 __half2float(tsm[(size_t)(s + 1) * 130 + er]));
            uint32_t p1 = pack2h(__half2float(tsm[(size_t)(s + 2) * 130 + er]),
                                 __half2float(tsm[(size_t)(s + 3) * 130 + er]));
            *(uint2*)(g_Vth + ((size_t)bh * ND + n0 + er) * NS + m0 + s) = make_uint2(p0, p1);
        }
    }
}

// ---------------------------------------------------------------------------
// Kernel: FUSED scores + softmax.  grid (8, 1, 64): CTA owns 128 full rows.
// Loops 8 K-tiles; per tile stores fp16 logits + online (M,S) update from
// register accumulators.  Pass 2 re-reads own logits (L2-hot), normalizes
// in place.  Stored logits and sums are bit-consistent (fp16-rounded).
// ---------------------------------------------------------------------------
__global__ __launch_bounds__(256, 2) void scores_g()
{
    extern __shared__ char sm[];
    float* rmax = (float*)(sm + SMEM_G);            // [128][4]
    float* rsum = (float*)(sm + SMEM_G + 2048);     // [128][4]
    float* Mrow = (float*)(sm + SMEM_G + 4096);     // [128]
    float* Srow = (float*)(sm + SMEM_G + 4608);     // [128]

    int bh = blockIdx.z, m0 = blockIdx.x * 128;
    int t = threadIdx.x, lane = t & 31, wid = t >> 5;
    int wm = wid & 1, wn = wid >> 1;

    if (t < 128) { Mrow[t] = -1e30f; Srow[t] = 0.f; }

    const __half* Abase = g_Qh + ((size_t)bh * NS + m0) * ND;

    for (int nt = 0; nt < 8; nt++) {
        float acc[4][4][4];
        mma_gemm1(Abase, g_Kh + ((size_t)bh * NS + nt * 128) * ND, ND, ND, 8, acc, sm);

        // store fp16 logits; replace acc with the rounded values
        #pragma unroll
        for (int mf = 0; mf < 4; mf++) {
            int r = m0 + wm * 64 + mf * 16 + (lane >> 2);
            #pragma unroll
            for (int nf = 0; nf < 4; nf++) {
                int cc = nt * 128 + wn * 32 + nf * 8 + ((lane & 3) << 1);
                __half h0 = __float2half_rn(acc[mf][nf][0]);
                __half h1 = __float2half_rn(acc[mf][nf][1]);
                __half h2 = __float2half_rn(acc[mf][nf][2]);
                __half h3 = __float2half_rn(acc[mf][nf][3]);
                __half* d0 = g_Ph + ((size_t)bh * NS + r) * NS + cc;
                *(uint32_t*)d0 =
                    (uint32_t)__half_as_ushort(h0) | ((uint32_t)__half_as_ushort(h1) << 16);
                *(uint32_t*)(d0 + 8 * NS) =
                    (uint32_t)__half_as_ushort(h2) | ((uint32_t)__half_as_ushort(h3) << 16);
                acc[mf][nf][0] = __half2float(h0); acc[mf][nf][1] = __half2float(h1);
                acc[mf][nf][2] = __half2float(h2); acc[mf][nf][3] = __half2float(h3);
            }
        }

        // per-row tile max (register + shfl over 4-lane column group)
        float pm[4][2];
        #pragma unroll
        for (int mf = 0; mf < 4; mf++)
            #pragma unroll
            for (int hh = 0; hh < 2; hh++) {
                float v = -1e30f;
                #pragma unroll
                for (int nf = 0; nf < 4; nf++)
                    v = fmaxf(v, fmaxf(acc[mf][nf][2*hh], acc[mf][nf][2*hh + 1]));
                v = fmaxf(v, __shfl_xor_sync(0xffffffffu, v, 1));
                v = fmaxf(v, __shfl_xor_sync(0xffffffffu, v, 2));
                pm[mf][hh] = v;
            }
        if ((lane & 3) == 0) {
            #pragma unroll
            for (int mf = 0; mf < 4; mf++)
                #pragma unroll
                for (int hh = 0; hh < 2; hh++)
                    rmax[(wm * 64 + mf * 16 + (lane >> 2) + 8 * hh) * 4 + wn] = pm[mf][hh];
        }
        __syncthreads();

        // per-row exp sums against the finalized tile max
        #pragma unroll
        for (int mf = 0; mf < 4; mf++)
            #pragma unroll
            for (int hh = 0; hh < 2; hh++) {
                int row = wm * 64 + mf * 16 + (lane >> 2) + 8 * hh;
                float tm = fmaxf(fmaxf(rmax[row*4], rmax[row*4+1]),
                                 fmaxf(rmax[row*4+2], rmax[row*4+3]));
                float s = 0.f;
                #pragma unroll
                for (int nf = 0; nf < 4; nf++)
                    s += __expf(acc[mf][nf][2*hh] - tm) + __expf(acc[mf][nf][2*hh+1] - tm);
                s += __shfl_xor_sync(0xffffffffu, s, 1);
                s += __shfl_xor_sync(0xffffffffu, s, 2);
                if ((lane & 3) == 0) rsum[row * 4 + wn] = s;
            }
        __syncthreads();

        // online (M,S) update, one thread per row
        if (t < 128) {
            float tm = fmaxf(fmaxf(rmax[t*4], rmax[t*4+1]),
                             fmaxf(rmax[t*4+2], rmax[t*4+3]));
            float ts = rsum[t*4] + rsum[t*4+1] + rsum[t*4+2] + rsum[t*4+3];
            float M = Mrow[t];
            float Mn = fmaxf(M, tm);
            Srow[t] = Srow[t] * __expf(M - Mn) + ts * __expf(tm - Mn);
            Mrow[t] = Mn;
        }
        // next mainloop's first barrier orders these smem writes
    }
    __syncthreads();

    // pass 2: normalize own rows in place (L2-hot). warp wid: rows wid*16..+15
    #pragma unroll
    for (int j = 0; j < 16; j++) {
        int rl = wid * 16 + j;
        float M = Mrow[rl], inv = 1.0f / Srow[rl];
        uint4* pr = (uint4*)(g_Ph + ((size_t)bh * NS + m0 + rl) * NS);
        #pragma unroll
        for (int jj = 0; jj < 4; jj++) {
            uint4 d = pr[lane + (jj << 5)];
            uint32_t w[4] = {d.x, d.y, d.z, d.w};
            #pragma unroll
            for (int k = 0; k < 4; k++) {
                float2 p = __half22float2(*(__half2*)&w[k]);
                w[k] = pack2h(__expf(p.x - M) * inv, __expf(p.y - M) * inv);
            }
            pr[lane + (jj << 5)] = make_uint4(w[0], w[1], w[2], w[3]);
        }
    }
}

// ---------------------------------------------------------------------------
// Kernel: O = P @ V (B = V^T).  grid (8, 2, 64) -> concat layout
// ---------------------------------------------------------------------------
__global__ __launch_bounds__(256, 2) void pv_g()
{
    extern __shared__ char sm[];
    int bh = blockIdx.z, b = bh >> 3, h = bh & 7;
    int m0 = blockIdx.x * 128, n0 = blockIdx.y * 128;
    float acc[4][4][4];
    mma_gemm1(g_Ph + ((size_t)bh * NS + m0) * NS,
              g_Vth + (size_t)bh * ND * NS + (size_t)n0 * NS, NS, NS, 32, acc, sm);

    int lane = threadIdx.x & 31, wid = threadIdx.x >> 5;
    int wm = wid & 1, wn = wid >> 1;
    #pragma unroll
    for (int mf = 0; mf < 4; mf++) {
        int r = m0 + wm * 64 + mf * 16 + (lane >> 2);
        #pragma unroll
        for (int nf = 0; nf < 4; nf++) {
            int cc = n0 + wn * 32 + nf * 8 + ((lane & 3) << 1);
            size_t base0 = ((size_t)(b * NS + r)) * HD + h * ND + cc;
            size_t base1 = base0 + 8 * HD;
            *(uint32_t*)(g_Oh + base0) = pack2h(acc[mf][nf][0], acc[mf][nf][1]);
            *(uint32_t*)(g_Oh + base1) = pack2h(acc[mf][nf][2], acc[mf][nf][3]);
        }
    }
}

// ---------------------------------------------------------------------------
// Kernel: out = concat(O) @ Wp^T.  grid (64, 2, 1)
// ---------------------------------------------------------------------------
__global__ __launch_bounds__(256, 2) void proj_g(float* __restrict__ out)
{
    extern __shared__ char sm[];
    int m0 = blockIdx.x * 128, n0 = blockIdx.y * 128;
    float acc[4][4][4];
    mma_gemm1(g_Oh + (size_t)m0 * HD, g_Wph + (size_t)n0 * HD,
              HD, HD, 64, acc, sm);

    int lane = threadIdx.x & 31, wid = threadIdx.x >> 5;
    int wm = wid & 1, wn = wid >> 1;
    #pragma unroll
    for (int mf = 0; mf < 4; mf++) {
        int r = m0 + wm * 64 + mf * 16 + (lane >> 2);
        #pragma unroll
        for (int nf = 0; nf < 4; nf++) {
            int cc = n0 + wn * 32 + nf * 8 + ((lane & 3) << 1);
            float* d0 = out + (size_t)r * ND + cc;
            *(float2*)d0 = make_float2(acc[mf][nf][0], acc[mf][nf][1]);
            *(float2*)(d0 + 8 * ND) = make_float2(acc[mf][nf][2], acc[mf][nf][3]);
        }
    }
}

// ---------------------------------------------------------------------------
extern "C" void kernel_launch(void* const* d_in, const int* in_sizes, int n_in,
                              void* d_out, int out_size)
{
    const float* x  = (const float*)d_in[0];
    const float* Wq = (const float*)d_in[1];
    const float* Wk = (const float*)d_in[2];
    const float* Wv = (const float*)d_in[3];
    const float* bq = (const float*)d_in[4];
    const float* bk = (const float*)d_in[5];
    const float* bv = (const float*)d_in[6];
    const float* Wp = (const float*)d_in[7];
    float* out = (float*)d_out;

    cudaFuncSetAttribute(qkv_g,    cudaFuncAttributeMaxDynamicSharedMemorySize, SMEM_G);
    cudaFuncSetAttribute(scores_g, cudaFuncAttributeMaxDynamicSharedMemorySize, SMEM_S);
    cudaFuncSetAttribute(pv_g,     cudaFuncAttributeMaxDynamicSharedMemorySize, SMEM_G);
    cudaFuncSetAttribute(proj_g,   cudaFuncAttributeMaxDynamicSharedMemorySize, SMEM_G);

    cvt_all<<<4096, 256>>>(x, Wq, Wk, Wv, Wp);

    dim3 gq(8, 2, 192);
    qkv_g<<<gq, 256, SMEM_G>>>(bq, bk, bv);

    dim3 gs(8, 1, 64);
    scores_g<<<gs, 256, SMEM_S>>>();

    dim3 gp(8, 2, 64);
    pv_g<<<gp, 256, SMEM_G>>>();

    dim3 go(64, 2, 1);
    proj_g<<<go, 256, SMEM_G>>>(out);
}

// round 17
// speedup vs baseline: 1.1173x; 1.1173x over previous
#include <cuda_runtime.h>
#include <cuda_fp16.h>
#include <cstdint>

#define NS 1024
#define ND 256
#define NH 8
#define HD 2048

// ---------------- scratch (static device memory; no allocs) ----------------
__device__ __half g_Xh[2097152];
__device__ __half g_Wqh[524288], g_Wkh[524288], g_Wvh[524288], g_Wph[524288];
__device__ __half g_Qh[16777216], g_Kh[16777216];
__device__ __half g_Vth[16777216];                                // V transposed [bh, e, t]
__device__ __half g_Ph[67108864];                                 // fp16 logits -> probs (in place)
__device__ __half g_Oh[16777216];                                 // [B*S, H*D] concat layout

// ---------------- helpers ----------------
__device__ __forceinline__ uint32_t smem_u32(const void* p) {
    uint32_t a;
    asm("{ .reg .u64 t; cvta.to.shared.u64 t, %1; cvt.u32.u64 %0, t; }" : "=r"(a) : "l"(p));
    return a;
}

__device__ __forceinline__ uint32_t pack2h(float a, float b) {
    __half h0 = __float2half_rn(a), h1 = __float2half_rn(b);
    return (uint32_t)__half_as_ushort(h0) | ((uint32_t)__half_as_ushort(h1) << 16);
}

#define CP_ASYNC16(saddr, gptr) \
    asm volatile("cp.async.cg.shared.global [%0], [%1], 16;" :: "r"(saddr), "l"(gptr))
#define CP_COMMIT() asm volatile("cp.async.commit_group;")
#define CP_WAIT2()  asm volatile("cp.async.wait_group 2;")
#define CP_WAIT1()  asm volatile("cp.async.wait_group 1;")
#define CP_WAIT0()  asm volatile("cp.async.wait_group 0;")
#define LDMX4(r0, r1, r2, r3, addr) \
    asm volatile("ldmatrix.sync.aligned.m8n8.x4.shared.b16 {%0,%1,%2,%3}, [%4];" \
        : "=r"(r0), "=r"(r1), "=r"(r2), "=r"(r3) : "r"(addr))
#define MMA16816(acc, af, b0, b1) \
    asm volatile("mma.sync.aligned.m16n8k16.row.col.f32.f16.f16.f32 " \
        "{%0,%1,%2,%3}, {%4,%5,%6,%7}, {%8,%9}, {%0,%1,%2,%3};" \
        : "+f"((acc)[0]), "+f"((acc)[1]), "+f"((acc)[2]), "+f"((acc)[3]) \
        : "r"((af)[0]), "r"((af)[1]), "r"((af)[2]), "r"((af)[3]), "r"(b0), "r"(b1))

// ---------------------------------------------------------------------------
// Single-product fp16 GEMM mainloop (NF=4): C[128,128] NT, fp32 accum.
// 8 warps 2(M) x 4(N); warp tile 64 x 32.  BK=32.  4-STAGE cp.async ring
// (steady-state wait_group 2 => two loads in flight), register pointer
// rotation, precomputed offsets, one barrier per chunk.
// Stage layout (bytes): sA [128][40]h @0 (10240), sB [128][40]h @10240.
// STAGE = 20480.  80 KB/CTA -> still 2 CTAs/SM (acc = 64 regs).
// ---------------------------------------------------------------------------
__device__ __forceinline__ void mma_gemm1(
    const __half* __restrict__ A, const __half* __restrict__ B,
    int ldA, int ldB, int ksteps, float acc[4][4][4], char* sm)
{
    constexpr int STAGE = 20480;

    int t = threadIdx.x;
    int lane = t & 31, wid = t >> 5;
    int wm = wid & 1, wn = wid >> 1;

    #pragma unroll
    for (int mf = 0; mf < 4; mf++)
        #pragma unroll
        for (int nf = 0; nf < 4; nf++)
            #pragma unroll
            for (int e = 0; e < 4; e++) acc[mf][nf][e] = 0.f;

    uint32_t sb = smem_u32(sm);

    int r1 = t >> 2,          q1 = t & 3;
    int r2 = (t + 256) >> 2,  q2 = (t + 256) & 3;
    uint32_t stA1 = (uint32_t)(r1 * 80 + q1 * 16);
    uint32_t stA2 = (uint32_t)(r2 * 80 + q2 * 16);
    uint32_t stB1 = 10240 + stA1;
    uint32_t stB2 = 10240 + stA2;

    const __half* gA1 = A + (size_t)r1 * ldA + q1 * 8;
    const __half* gA2 = A + (size_t)r2 * ldA + q2 * 8;
    const __half* gB1 = B + (size_t)r1 * ldB + q1 * 8;
    const __half* gB2 = B + (size_t)r2 * ldB + q2 * 8;

    uint32_t aoff[2][4], boff[2][2];
    #pragma unroll
    for (int k16 = 0; k16 < 2; k16++) {
        #pragma unroll
        for (int mf = 0; mf < 4; mf++) {
            int row = wm * 64 + mf * 16 + (lane & 15);
            int ko  = k16 * 16 + (lane >> 4) * 8;
            aoff[k16][mf] = (uint32_t)(row * 80 + ko * 2);
        }
        #pragma unroll
        for (int p = 0; p < 2; p++) {
            int nrow = wn * 32 + p * 16 + (lane & 7) + ((lane >> 4) << 3);
            int ko   = k16 * 16 + ((lane >> 3) & 1) * 8;
            boff[k16][p] = (uint32_t)(10240 + nrow * 80 + ko * 2);
        }
    }

    auto load_tile = [&](uint32_t base) {
        CP_ASYNC16(base + stA1, gA1);
        CP_ASYNC16(base + stA2, gA2);
        CP_ASYNC16(base + stB1, gB1);
        CP_ASYNC16(base + stB2, gB2);
        CP_COMMIT();
        gA1 += 32; gA2 += 32; gB1 += 32; gB2 += 32;
    };

    uint32_t s0 = sb, s1 = sb + STAGE, s2 = sb + 2 * STAGE, s3 = sb + 3 * STAGE;
    load_tile(s0);
    if (ksteps > 1) load_tile(s1);
    if (ksteps > 2) load_tile(s2);

    for (int c = 0; c < ksteps; c++) {
        if (c + 3 <= ksteps)      { CP_WAIT2(); }
        else if (c + 2 <= ksteps) { CP_WAIT1(); }
        else                      { CP_WAIT0(); }
        __syncthreads();                 // orders compute(c-1) before rewrite of its buffer
        if (c + 3 < ksteps) load_tile(s3);

        #pragma unroll
        for (int k16 = 0; k16 < 2; k16++) {
            uint32_t af[4][4];
            #pragma unroll
            for (int mf = 0; mf < 4; mf++)
                LDMX4(af[mf][0], af[mf][1], af[mf][2], af[mf][3], s0 + aoff[k16][mf]);
            uint32_t bf[4][2];
            #pragma unroll
            for (int p = 0; p < 2; p++) {
                uint32_t rr0, rr1, rr2, rr3;
                LDMX4(rr0, rr1, rr2, rr3, s0 + boff[k16][p]);
                bf[2*p][0] = rr0; bf[2*p][1] = rr1;
                bf[2*p+1][0] = rr2; bf[2*p+1][1] = rr3;
            }
            #pragma unroll
            for (int mf = 0; mf < 4; mf++)
                #pragma unroll
                for (int nf = 0; nf < 4; nf++)
                    MMA16816(acc[mf][nf], af[mf], bf[nf][0], bf[nf][1]);
        }
        uint32_t tmp = s0; s0 = s1; s1 = s2; s2 = s3; s3 = tmp;
    }
}

#define SMEM_G (4 * 20480)   // 81920

// ---------------------------------------------------------------------------
// Kernel: fused fp32 -> fp16 convert for all 5 inputs.  grid 4096, block 256
// ---------------------------------------------------------------------------
__global__ __launch_bounds__(256) void cvt_all(
    const float* __restrict__ x,  const float* __restrict__ Wq,
    const float* __restrict__ Wk, const float* __restrict__ Wv,
    const float* __restrict__ Wp)
{
    int blk = blockIdx.x;
    const float* src;
    __half* dst;
    int local;
    if (blk < 2048)      { src = x;  dst = g_Xh;  local = blk; }
    else if (blk < 2560) { src = Wq; dst = g_Wqh; local = blk - 2048; }
    else if (blk < 3072) { src = Wk; dst = g_Wkh; local = blk - 2560; }
    else if (blk < 3584) { src = Wv; dst = g_Wvh; local = blk - 3072; }
    else                 { src = Wp; dst = g_Wph; local = blk - 3584; }
    int i = local * 256 + threadIdx.x;
    float4 v = *(const float4*)(src + 4 * (size_t)i);
    *(uint2*)((char*)dst + 8 * (size_t)i) = make_uint2(pack2h(v.x, v.y), pack2h(v.z, v.w));
}

// ---------------------------------------------------------------------------
// Kernel: QKV projection.  grid (8, 2, 192): z = qkv*64 + b*8 + h
// Q pre-scaled by 2^-4 (exact).  V stored TRANSPOSED into g_Vth via smem.
// ---------------------------------------------------------------------------
__global__ __launch_bounds__(256, 2) void qkv_g(
    const float* __restrict__ bq, const float* __restrict__ bk, const float* __restrict__ bv)
{
    extern __shared__ char sm[];
    int z = blockIdx.z, qkv = z >> 6, bh = z & 63, b = bh >> 3, h = bh & 7;
    int m0 = blockIdx.x * 128, n0 = blockIdx.y * 128;

    const __half* Wh = (qkv == 0) ? g_Wqh : (qkv == 1) ? g_Wkh : g_Wvh;
    const float* bias = ((qkv == 0) ? bq : (qkv == 1) ? bk : bv) + h * ND + n0;

    float acc[4][4][4];
    mma_gemm1(g_Xh + ((size_t)b * NS + m0) * ND,
              Wh + (size_t)h * ND * ND + (size_t)n0 * ND, ND, ND, 8, acc, sm);

    int lane = threadIdx.x & 31, wid = threadIdx.x >> 5;
    int wm = wid & 1, wn = wid >> 1;

    if (qkv < 2) {
        __half* Oh = (qkv == 0) ? g_Qh : g_Kh;
        float scale = (qkv == 0) ? 0.0625f : 1.0f;
        #pragma unroll
        for (int mf = 0; mf < 4; mf++) {
            int r = m0 + wm * 64 + mf * 16 + (lane >> 2);
            #pragma unroll
            for (int nf = 0; nf < 4; nf++) {
                int cc = wn * 32 + nf * 8 + ((lane & 3) << 1);
                float2 bb = *(const float2*)(bias + cc);
                size_t base0 = ((size_t)bh * NS + r) * ND + n0 + cc;
                size_t base1 = base0 + 8 * ND;
                *(uint32_t*)(Oh + base0) = pack2h((acc[mf][nf][0] + bb.x) * scale,
                                                  (acc[mf][nf][1] + bb.y) * scale);
                *(uint32_t*)(Oh + base1) = pack2h((acc[mf][nf][2] + bb.x) * scale,
                                                  (acc[mf][nf][3] + bb.y) * scale);
            }
        }
    } else {
        // V: bounce through smem [128][130] halves and store transposed.
        __syncthreads();                      // mainloop smem reads done
        __half* tsm = (__half*)sm;            // row stride 130 halves
        #pragma unroll
        for (int mf = 0; mf < 4; mf++) {
            int rl = wm * 64 + mf * 16 + (lane >> 2);
            #pragma unroll
            for (int nf = 0; nf < 4; nf++) {
                int cc = wn * 32 + nf * 8 + ((lane & 3) << 1);
                float2 bb = *(const float2*)(bias + cc);
                *(uint32_t*)(tsm + (size_t)rl * 130 + cc) =
                    pack2h(acc[mf][nf][0] + bb.x, acc[mf][nf][1] + bb.y);
                *(uint32_t*)(tsm + (size_t)(rl + 8) * 130 + cc) =
                    pack2h(acc[mf][nf][2] + bb.x, acc[mf][nf][3] + bb.y);
            }
        }
        __syncthreads();
        #pragma unroll
        for (int j = 0; j < 16; j++) {
            int er = wid * 16 + j;
            int s = lane * 4;
            uint32_t p0 = pack2h(__half2float(tsm[(size_t)(s + 0) * 130 + er]),
                                 __half2float(tsm[(size_t)(s + 1) * 130 + er]));
            uint32_t p1 = pack2h(__half2float(tsm[(size_t)(s + 2) * 130 + er]),
                                 __half2float(tsm[(size_t)(s + 3) * 130 + er]));
            *(uint2*)(g_Vth + ((size_t)bh * ND + n0 + er) * NS + m0 + s) = make_uint2(p0, p1);
        }
    }
}

// ---------------------------------------------------------------------------
// Kernel: scores = (Q/16) K^T -> fp16 logits.  grid (8, 8, 64)
// ---------------------------------------------------------------------------
__global__ __launch_bounds__(256, 2) void scores_g()
{
    extern __shared__ char sm[];
    int bh = blockIdx.z, m0 = blockIdx.x * 128, n0 = blockIdx.y * 128;
    float acc[4][4][4];
    mma_gemm1(g_Qh + ((size_t)bh * NS + m0) * ND,
              g_Kh + ((size_t)bh * NS + n0) * ND, ND, ND, 8, acc, sm);

    int lane = threadIdx.x & 31, wid = threadIdx.x >> 5;
    int wm = wid & 1, wn = wid >> 1;
    #pragma unroll
    for (int mf = 0; mf < 4; mf++) {
        int r = m0 + wm * 64 + mf * 16 + (lane >> 2);
        #pragma unroll
        for (int nf = 0; nf < 4; nf++) {
            int cc = n0 + wn * 32 + nf * 8 + ((lane & 3) << 1);
            __half* d0 = g_Ph + ((size_t)bh * NS + r) * NS + cc;
            *(uint32_t*)d0 = pack2h(acc[mf][nf][0], acc[mf][nf][1]);
            *(uint32_t*)(d0 + 8 * NS) = pack2h(acc[mf][nf][2], acc[mf][nf][3]);
        }
    }
}

// ---------------------------------------------------------------------------
// Kernel: warp-per-row in-place softmax on fp16 logits.  grid 8192, block 256
// Pure shfl reductions — no smem, no barriers.
// ---------------------------------------------------------------------------
__global__ __launch_bounds__(256) void softmax_kernel()
{
    int wid = threadIdx.x >> 5, lane = threadIdx.x & 31;
    size_t row = (size_t)blockIdx.x * 8 + wid;
    uint4* pr = (uint4*)(g_Ph + row * NS);

    uint4 d[4];
    #pragma unroll
    for (int j = 0; j < 4; j++) d[j] = pr[lane + (j << 5)];

    float f[32];
    #pragma unroll
    for (int j = 0; j < 4; j++) {
        uint32_t w[4] = {d[j].x, d[j].y, d[j].z, d[j].w};
        #pragma unroll
        for (int k = 0; k < 4; k++) {
            float2 p = __half22float2(*(__half2*)&w[k]);
            f[j * 8 + k * 2]     = p.x;
            f[j * 8 + k * 2 + 1] = p.y;
        }
    }

    float m = f[0];
    #pragma unroll
    for (int i = 1; i < 32; i++) m = fmaxf(m, f[i]);
    #pragma unroll
    for (int o = 16; o > 0; o >>= 1) m = fmaxf(m, __shfl_xor_sync(0xffffffffu, m, o));

    float s = 0.f;
    #pragma unroll
    for (int i = 0; i < 32; i++) { f[i] = __expf(f[i] - m); s += f[i]; }
    #pragma unroll
    for (int o = 16; o > 0; o >>= 1) s += __shfl_xor_sync(0xffffffffu, s, o);
    float inv = 1.0f / s;

    #pragma unroll
    for (int j = 0; j < 4; j++) {
        uint4 o4;
        o4.x = pack2h(f[j*8+0] * inv, f[j*8+1] * inv);
        o4.y = pack2h(f[j*8+2] * inv, f[j*8+3] * inv);
        o4.z = pack2h(f[j*8+4] * inv, f[j*8+5] * inv);
        o4.w = pack2h(f[j*8+6] * inv, f[j*8+7] * inv);
        pr[lane + (j << 5)] = o4;
    }
}

// ---------------------------------------------------------------------------
// Kernel: O = P @ V (B = V^T).  grid (8, 2, 64) -> concat layout
// ---------------------------------------------------------------------------
__global__ __launch_bounds__(256, 2) void pv_g()
{
    extern __shared__ char sm[];
    int bh = blockIdx.z, b = bh >> 3, h = bh & 7;
    int m0 = blockIdx.x * 128, n0 = blockIdx.y * 128;
    float acc[4][4][4];
    mma_gemm1(g_Ph + ((size_t)bh * NS + m0) * NS,
              g_Vth + (size_t)bh * ND * NS + (size_t)n0 * NS, NS, NS, 32, acc, sm);

    int lane = threadIdx.x & 31, wid = threadIdx.x >> 5;
    int wm = wid & 1, wn = wid >> 1;
    #pragma unroll
    for (int mf = 0; mf < 4; mf++) {
        int r = m0 + wm * 64 + mf * 16 + (lane >> 2);
        #pragma unroll
        for (int nf = 0; nf < 4; nf++) {
            int cc = n0 + wn * 32 + nf * 8 + ((lane & 3) << 1);
            size_t base0 = ((size_t)(b * NS + r)) * HD + h * ND + cc;
            size_t base1 = base0 + 8 * HD;
            *(uint32_t*)(g_Oh + base0) = pack2h(acc[mf][nf][0], acc[mf][nf][1]);
            *(uint32_t*)(g_Oh + base1) = pack2h(acc[mf][nf][2], acc[mf][nf][3]);
        }
    }
}

// ---------------------------------------------------------------------------
// Kernel: out = concat(O) @ Wp^T.  grid (64, 2, 1)
// ---------------------------------------------------------------------------
__global__ __launch_bounds__(256, 2) void proj_g(float* __restrict__ out)
{
    extern __shared__ char sm[];
    int m0 = blockIdx.x * 128, n0 = blockIdx.y * 128;
    float acc[4][4][4];
    mma_gemm1(g_Oh + (size_t)m0 * HD, g_Wph + (size_t)n0 * HD,
              HD, HD, 64, acc, sm);

    int lane = threadIdx.x & 31, wid = threadIdx.x >> 5;
    int wm = wid & 1, wn = wid >> 1;
    #pragma unroll
    for (int mf = 0; mf < 4; mf++) {
        int r = m0 + wm * 64 + mf * 16 + (lane >> 2);
        #pragma unroll
        for (int nf = 0; nf < 4; nf++) {
            int cc = n0 + wn * 32 + nf * 8 + ((lane & 3) << 1);
            float* d0 = out + (size_t)r * ND + cc;
            *(float2*)d0 = make_float2(acc[mf][nf][0], acc[mf][nf][1]);
            *(float2*)(d0 + 8 * ND) = make_float2(acc[mf][nf][2], acc[mf][nf][3]);
        }
    }
}

// ---------------------------------------------------------------------------
extern "C" void kernel_launch(void* const* d_in, const int* in_sizes, int n_in,
                              void* d_out, int out_size)
{
    const float* x  = (const float*)d_in[0];
    const float* Wq = (const float*)d_in[1];
    const float* Wk = (const float*)d_in[2];
    const float* Wv = (const float*)d_in[3];
    const float* bq = (const float*)d_in[4];
    const float* bk = (const float*)d_in[5];
    const float* bv = (const float*)d_in[6];
    const float* Wp = (const float*)d_in[7];
    float* out = (float*)d_out;

    cudaFuncSetAttribute(qkv_g,    cudaFuncAttributeMaxDynamicSharedMemorySize, SMEM_G);
    cudaFuncSetAttribute(scores_g, cudaFuncAttributeMaxDynamicSharedMemorySize, SMEM_G);
    cudaFuncSetAttribute(pv_g,     cudaFuncAttributeMaxDynamicSharedMemorySize, SMEM_G);
    cudaFuncSetAttribute(proj_g,   cudaFuncAttributeMaxDynamicSharedMemorySize, SMEM_G);

    cvt_all<<<4096, 256>>>(x, Wq, Wk, Wv, Wp);

    dim3 gq(8, 2, 192);
    qkv_g<<<gq, 256, SMEM_G>>>(bq, bk, bv);

    dim3 gs(8, 8, 64);
    scores_g<<<gs, 256, SMEM_G>>>();

    softmax_kernel<<<8192, 256>>>();

    dim3 gp(8, 2, 64);
    pv_g<<<gp, 256, SMEM_G>>>();

    dim3 go(64, 2, 1);
    proj_g<<<go, 256, SMEM_G>>>(out);
}